// round 1
// baseline (speedup 1.0000x reference)
#include <cuda_runtime.h>
#include <math.h>

// Problem constants
#define DM    1024
#define SEQ   2048
#define NB    4
#define NH    16
#define HD    64
#define MROWS (NB*SEQ)          // 8192

// Scratch (device globals; no allocations allowed)
__device__ float g_q[NB*NH*SEQ*HD];
__device__ float g_k[NB*NH*SEQ*HD];
__device__ float g_v[NB*NH*SEQ*HD];
__device__ float g_attn[NB*SEQ*DM];

// ---------------------------------------------------------------------------
// GEMM: C[M=8192, N=1024] = A[M,K=1024] @ W[N,K]^T + bias (+ bias2)
// BM=BN=128, BK=8, 256 threads, 8x8 register microtile per thread.
// head_layout=1: write C[m][n] to [(b*16+h)*SEQ + s]*HD + d layout (b=m>>11,
// s=m&2047, h=n>>6, d=n&63) so attention reads are contiguous.
// ---------------------------------------------------------------------------
__global__ __launch_bounds__(256) void gemm_nt_kernel(
    const float* __restrict__ A, const float* __restrict__ W,
    const float* __restrict__ bias, const float* __restrict__ bias2,
    float* __restrict__ C, int head_layout)
{
    __shared__ float As[8][132];   // pad 132: 4*132 % 32 = 16 -> conflict-free STS, 16B aligned
    __shared__ float Bs[8][132];

    const int t  = threadIdx.x;
    const int tx = t & 15;
    const int ty = t >> 4;
    const int m0 = blockIdx.y * 128;
    const int n0 = blockIdx.x * 128;

    const int lr = t >> 1;          // 0..127: tile row this thread loads
    const int lk = (t & 1) * 4;     // 0 or 4: k-offset of its float4

    const float* Aptr = A + (size_t)(m0 + lr) * DM + lk;
    const float* Wptr = W + (size_t)(n0 + lr) * DM + lk;

    float acc[8][8];
#pragma unroll
    for (int i = 0; i < 8; i++)
#pragma unroll
        for (int j = 0; j < 8; j++) acc[i][j] = 0.f;

    for (int kt = 0; kt < DM; kt += 8) {
        float4 av = *(const float4*)(Aptr + kt);
        float4 wv = *(const float4*)(Wptr + kt);
        As[lk+0][lr] = av.x; As[lk+1][lr] = av.y;
        As[lk+2][lr] = av.z; As[lk+3][lr] = av.w;
        Bs[lk+0][lr] = wv.x; Bs[lk+1][lr] = wv.y;
        Bs[lk+2][lr] = wv.z; Bs[lk+3][lr] = wv.w;
        __syncthreads();

#pragma unroll
        for (int kk = 0; kk < 8; kk++) {
            float4 a0 = *(const float4*)&As[kk][ty*8];
            float4 a1 = *(const float4*)&As[kk][ty*8+4];
            float4 b0 = *(const float4*)&Bs[kk][tx*8];
            float4 b1 = *(const float4*)&Bs[kk][tx*8+4];
            float a[8] = {a0.x,a0.y,a0.z,a0.w,a1.x,a1.y,a1.z,a1.w};
            float b[8] = {b0.x,b0.y,b0.z,b0.w,b1.x,b1.y,b1.z,b1.w};
#pragma unroll
            for (int i = 0; i < 8; i++)
#pragma unroll
                for (int j = 0; j < 8; j++)
                    acc[i][j] += a[i] * b[j];
        }
        __syncthreads();
    }

#pragma unroll
    for (int i = 0; i < 8; i++) {
        const int m = m0 + ty*8 + i;
#pragma unroll
        for (int j = 0; j < 8; j++) {
            const int n = n0 + tx*8 + j;
            float v = acc[i][j] + bias[n];
            if (bias2) v += bias2[n];
            size_t idx;
            if (head_layout) {
                idx = ((size_t)((m >> 11) * NH + (n >> 6))) * ((size_t)SEQ * HD)
                    + (size_t)(m & (SEQ-1)) * HD + (n & (HD-1));
            } else {
                idx = (size_t)m * DM + n;
            }
            C[idx] = v;
        }
    }
}

// ---------------------------------------------------------------------------
// Streaming attention (flash-style, fp32).
// Grid: (SEQ/64, NB*NH). CTA: 64 query rows of one (b,h).
// Thread t: row r = t>>2, column/d quarter c0 = (t&3)*16.
// smem: Qs[64][64], Kt[64][64] (K transposed: [d][j]), Vs[64][64], Ps[64][64].
// ---------------------------------------------------------------------------
__global__ __launch_bounds__(256) void attn_kernel(float* __restrict__ out)
{
    extern __shared__ float sm[];
    float (*Qs)[64] = (float(*)[64])(sm);
    float (*Kt)[64] = (float(*)[64])(sm + 64*64);
    float (*Vs)[64] = (float(*)[64])(sm + 2*64*64);
    float (*Ps)[64] = (float(*)[64])(sm + 3*64*64);

    const int t  = threadIdx.x;
    const int r  = t >> 2;
    const int c0 = (t & 3) * 16;
    const int bh = blockIdx.y;            // b*16 + h
    const int i0 = blockIdx.x * 64;

    const float* qg = g_q + (size_t)bh * SEQ * HD;
    const float* kg = g_k + (size_t)bh * SEQ * HD;
    const float* vg = g_v + (size_t)bh * SEQ * HD;

    // Load Q tile [64 rows x 64 d]
#pragma unroll
    for (int it = 0; it < 4; it++) {
        int fidx = t + it*256;            // float4 index, 1024 total
        int row  = fidx >> 4;
        int c4   = (fidx & 15) * 4;
        *(float4*)&Qs[row][c4] = *(const float4*)&qg[(i0+row)*HD + c4];
    }

    float o[16];
#pragma unroll
    for (int d = 0; d < 16; d++) o[d] = 0.f;
    float m_i = -1e30f, l_i = 0.f;

    for (int j0 = 0; j0 < SEQ; j0 += 64) {
        // Load K tile transposed: Kt[d][j]
        {
            const int j  = t & 63;
            const int dg = (t >> 6) * 16;
#pragma unroll
            for (int i4 = 0; i4 < 4; i4++) {
                int d0 = dg + i4*4;
                float4 kv = *(const float4*)&kg[(j0+j)*HD + d0];
                Kt[d0+0][j] = kv.x; Kt[d0+1][j] = kv.y;
                Kt[d0+2][j] = kv.z; Kt[d0+3][j] = kv.w;
            }
        }
        // Load V tile: Vs[j][d]
#pragma unroll
        for (int it = 0; it < 4; it++) {
            int fidx = t + it*256;
            int row  = fidx >> 4;
            int c4   = (fidx & 15) * 4;
            *(float4*)&Vs[row][c4] = *(const float4*)&vg[(j0+row)*HD + c4];
        }
        __syncthreads();

        // Scores: s[jj] = sum_d Qs[r][d] * Kt[d][c0+jj]
        float s[16];
#pragma unroll
        for (int jj = 0; jj < 16; jj++) s[jj] = 0.f;
#pragma unroll 8
        for (int d = 0; d < 64; d++) {
            float qv = Qs[r][d];
            float4 k0 = *(const float4*)&Kt[d][c0];
            float4 k1 = *(const float4*)&Kt[d][c0+4];
            float4 k2 = *(const float4*)&Kt[d][c0+8];
            float4 k3 = *(const float4*)&Kt[d][c0+12];
            s[0]  += qv*k0.x; s[1]  += qv*k0.y; s[2]  += qv*k0.z; s[3]  += qv*k0.w;
            s[4]  += qv*k1.x; s[5]  += qv*k1.y; s[6]  += qv*k1.z; s[7]  += qv*k1.w;
            s[8]  += qv*k2.x; s[9]  += qv*k2.y; s[10] += qv*k2.z; s[11] += qv*k2.w;
            s[12] += qv*k3.x; s[13] += qv*k3.y; s[14] += qv*k3.z; s[15] += qv*k3.w;
        }

        // Scale + band mask
        const int ig = i0 + r;
#pragma unroll
        for (int jj = 0; jj < 16; jj++) {
            int jg = j0 + c0 + jj;
            int dij = ig - jg; if (dij < 0) dij = -dij;
            float band = (dij <= 2) ? 0.1f : 0.f;
            s[jj] = s[jj] * 0.125f + band;
        }

        // Online softmax (row spread over 4 lanes: t, t^1, t^2 in same warp)
        float mt = s[0];
#pragma unroll
        for (int jj = 1; jj < 16; jj++) mt = fmaxf(mt, s[jj]);
        mt = fmaxf(mt, __shfl_xor_sync(0xffffffffu, mt, 1));
        mt = fmaxf(mt, __shfl_xor_sync(0xffffffffu, mt, 2));
        float m_new = fmaxf(m_i, mt);
        float alpha = __expf(m_i - m_new);
        float sum = 0.f;
#pragma unroll
        for (int jj = 0; jj < 16; jj++) {
            float p = __expf(s[jj] - m_new);
            Ps[r][c0 + jj] = p;
            sum += p;
        }
        sum += __shfl_xor_sync(0xffffffffu, sum, 1);
        sum += __shfl_xor_sync(0xffffffffu, sum, 2);
        l_i = l_i * alpha + sum;
        m_i = m_new;
#pragma unroll
        for (int dd = 0; dd < 16; dd++) o[dd] *= alpha;
        __syncwarp();

        // O[r][c0+dd] += sum_j Ps[r][j] * Vs[j][c0+dd]
#pragma unroll 8
        for (int j = 0; j < 64; j++) {
            float p = Ps[r][j];
            float4 v0 = *(const float4*)&Vs[j][c0];
            float4 v1 = *(const float4*)&Vs[j][c0+4];
            float4 v2 = *(const float4*)&Vs[j][c0+8];
            float4 v3 = *(const float4*)&Vs[j][c0+12];
            o[0]  += p*v0.x; o[1]  += p*v0.y; o[2]  += p*v0.z; o[3]  += p*v0.w;
            o[4]  += p*v1.x; o[5]  += p*v1.y; o[6]  += p*v1.z; o[7]  += p*v1.w;
            o[8]  += p*v2.x; o[9]  += p*v2.y; o[10] += p*v2.z; o[11] += p*v2.w;
            o[12] += p*v3.x; o[13] += p*v3.y; o[14] += p*v3.z; o[15] += p*v3.w;
        }
        __syncthreads();
    }

    // Write normalized output in flat [B,S,D] layout for the O-projection GEMM.
    const float inv = 1.f / l_i;
    const int b = bh >> 4, h = bh & 15;
    float* op = out + ((size_t)(b*SEQ + i0 + r)) * DM + h*HD + c0;
#pragma unroll
    for (int q4 = 0; q4 < 4; q4++) {
        float4 v;
        v.x = o[q4*4+0]*inv; v.y = o[q4*4+1]*inv;
        v.z = o[q4*4+2]*inv; v.w = o[q4*4+3]*inv;
        *(float4*)&op[q4*4] = v;
    }
}

// ---------------------------------------------------------------------------
extern "C" void kernel_launch(void* const* d_in, const int* in_sizes, int n_in,
                              void* d_out, int out_size)
{
    const float* x        = (const float*)d_in[0];
    // d_in[1] = ocr_context: shape-only in reference, unused
    const float* Wq       = (const float*)d_in[2];
    const float* bq       = (const float*)d_in[3];
    const float* Wk       = (const float*)d_in[4];
    const float* bk       = (const float*)d_in[5];
    const float* Wv       = (const float*)d_in[6];
    const float* bv       = (const float*)d_in[7];
    const float* Wo       = (const float*)d_in[8];
    const float* bo       = (const float*)d_in[9];
    const float* ocr_bias = (const float*)d_in[10];

    float *qp, *kp, *vp, *ap;
    cudaGetSymbolAddress((void**)&qp, g_q);
    cudaGetSymbolAddress((void**)&kp, g_k);
    cudaGetSymbolAddress((void**)&vp, g_v);
    cudaGetSymbolAddress((void**)&ap, g_attn);

    cudaFuncSetAttribute(attn_kernel,
                         cudaFuncAttributeMaxDynamicSharedMemorySize, 4*64*64*4);

    dim3 gemm_grid(DM/128, MROWS/128);   // (8, 64)
    gemm_nt_kernel<<<gemm_grid, 256>>>(x, Wq, bq, ocr_bias, qp, 1);
    gemm_nt_kernel<<<gemm_grid, 256>>>(x, Wk, bk, nullptr,  kp, 1);
    gemm_nt_kernel<<<gemm_grid, 256>>>(x, Wv, bv, nullptr,  vp, 1);

    dim3 attn_grid(SEQ/64, NB*NH);       // (32, 64)
    attn_kernel<<<attn_grid, 256, 4*64*64*4>>>(ap);

    gemm_nt_kernel<<<gemm_grid, 256>>>(ap, Wo, bo, nullptr, (float*)d_out, 0);
}

// round 6
// speedup vs baseline: 2.9278x; 2.9278x over previous
#include <cuda_runtime.h>
#include <math.h>

// Problem constants
#define DM    1024
#define SEQ   2048
#define NB    4
#define NH    16
#define HD    64
#define MROWS (NB*SEQ)          // 8192

// Attention tiling
#define BQ    128               // queries per CTA
#define BJ    64                // keys per tile
#define PADQ  132               // i-dim padded row (words)
#define PADK  68                // j/d-dim padded row (words)
#define ATTN_SMEM ((64*PADQ + 64*PADK + 64*PADK + 64*PADQ) * 4)   // 102400 B

// Scratch (device globals; no allocations allowed)
__device__ float g_q[NB*NH*SEQ*HD];
__device__ float g_k[NB*NH*SEQ*HD];
__device__ float g_v[NB*NH*SEQ*HD];
__device__ float g_attn[NB*SEQ*DM];

// ---------------------------------------------------------------------------
// GEMM: C[M=8192, N=1024] = A[M,K=1024] @ W[N,K]^T + bias (+ bias2)
// BM=BN=128, BK=8, 256 threads, 8x8 register microtile per thread.
// Register double-buffering: next tile's LDG.128s issued right after the
// barrier, overlapping the 512-FFMA compute body.
// head_layout=1: write C to [(b*16+h)*SEQ + s]*HD + d layout so attention
// reads are contiguous.
// ---------------------------------------------------------------------------
__global__ __launch_bounds__(256) void gemm_nt_kernel(
    const float* __restrict__ A, const float* __restrict__ W,
    const float* __restrict__ bias, const float* __restrict__ bias2,
    float* __restrict__ C, int head_layout)
{
    __shared__ float As[8][132];
    __shared__ float Bs[8][132];

    const int t  = threadIdx.x;
    const int tx = t & 15;
    const int ty = t >> 4;
    const int m0 = blockIdx.y * 128;
    const int n0 = blockIdx.x * 128;

    const int lr = t >> 1;          // 0..127: tile row this thread loads
    const int lk = (t & 1) * 4;     // 0 or 4: k-offset of its float4

    const float* Aptr = A + (size_t)(m0 + lr) * DM + lk;
    const float* Wptr = W + (size_t)(n0 + lr) * DM + lk;

    float acc[8][8];
#pragma unroll
    for (int i = 0; i < 8; i++)
#pragma unroll
        for (int j = 0; j < 8; j++) acc[i][j] = 0.f;

    float4 av = *(const float4*)(Aptr);
    float4 wv = *(const float4*)(Wptr);

    for (int kt = 0; kt < DM; kt += 8) {
        As[lk+0][lr] = av.x; As[lk+1][lr] = av.y;
        As[lk+2][lr] = av.z; As[lk+3][lr] = av.w;
        Bs[lk+0][lr] = wv.x; Bs[lk+1][lr] = wv.y;
        Bs[lk+2][lr] = wv.z; Bs[lk+3][lr] = wv.w;
        __syncthreads();

        // Prefetch next k-tile (overlaps with compute below)
        if (kt + 8 < DM) {
            av = *(const float4*)(Aptr + kt + 8);
            wv = *(const float4*)(Wptr + kt + 8);
        }

#pragma unroll
        for (int kk = 0; kk < 8; kk++) {
            float4 a0 = *(const float4*)&As[kk][ty*8];
            float4 a1 = *(const float4*)&As[kk][ty*8+4];
            float4 b0 = *(const float4*)&Bs[kk][tx*8];
            float4 b1 = *(const float4*)&Bs[kk][tx*8+4];
            float a[8] = {a0.x,a0.y,a0.z,a0.w,a1.x,a1.y,a1.z,a1.w};
            float b[8] = {b0.x,b0.y,b0.z,b0.w,b1.x,b1.y,b1.z,b1.w};
#pragma unroll
            for (int i = 0; i < 8; i++)
#pragma unroll
                for (int j = 0; j < 8; j++)
                    acc[i][j] += a[i] * b[j];
        }
        __syncthreads();
    }

#pragma unroll
    for (int i = 0; i < 8; i++) {
        const int m = m0 + ty*8 + i;
#pragma unroll
        for (int j = 0; j < 8; j++) {
            const int n = n0 + tx*8 + j;
            float v = acc[i][j] + bias[n];
            if (bias2) v += bias2[n];
            size_t idx;
            if (head_layout) {
                idx = ((size_t)((m >> 11) * NH + (n >> 6))) * ((size_t)SEQ * HD)
                    + (size_t)(m & (SEQ-1)) * HD + (n & (HD-1));
            } else {
                idx = (size_t)m * DM + n;
            }
            C[idx] = v;
        }
    }
}

// ---------------------------------------------------------------------------
// Streaming attention, register-blocked (flash-style, fp32).
// Grid: (SEQ/BQ, NB*NH). CTA: BQ=128 query rows of one (b,h), 256 threads.
// Thread (ty=t>>4, tx=t&15) owns an 8(row) x 4(col) microtile:
//   rows i = ty*8 + ii,   QK cols j = tx*4 + jj,   PV d-cols d = tx*4 + dd.
// smem (dynamic, 100KB):
//   Qt[d][i]  64 x 132   (Q transposed)
//   Kt[d][j]  64 x 68    (K transposed)
//   Vs[j][d]  64 x 68
//   Pt[j][i]  64 x 132   (P transposed)
// ---------------------------------------------------------------------------
__global__ __launch_bounds__(256, 2) void attn_kernel(float* __restrict__ out)
{
    extern __shared__ float sm[];
    float (*Qt)[PADQ] = (float(*)[PADQ])(sm);
    float (*Kt)[PADK] = (float(*)[PADK])(sm + 64*PADQ);
    float (*Vs)[PADK] = (float(*)[PADK])(sm + 64*PADQ + 64*PADK);
    float (*Pt)[PADQ] = (float(*)[PADQ])(sm + 64*PADQ + 2*64*PADK);

    const int t  = threadIdx.x;
    const int tx = t & 15;
    const int ty = t >> 4;
    const int bh = blockIdx.y;            // b*16 + h
    const int i0 = blockIdx.x * BQ;

    const float* qg = g_q + (size_t)bh * SEQ * HD;
    const float* kg = g_k + (size_t)bh * SEQ * HD;
    const float* vg = g_v + (size_t)bh * SEQ * HD;

    // Load Q tile transposed: Qt[d][i], i in [0,128), d in [0,64)
#pragma unroll
    for (int it = 0; it < 8; it++) {
        int fidx = t + it*256;             // 2048 float4s
        int i    = fidx >> 4;              // 0..127
        int d0   = (fidx & 15) * 4;
        float4 v = *(const float4*)&qg[(size_t)(i0 + i)*HD + d0];
        Qt[d0+0][i] = v.x; Qt[d0+1][i] = v.y;
        Qt[d0+2][i] = v.z; Qt[d0+3][i] = v.w;
    }

    float o[8][4];
    float m_i[8], l_i[8];
#pragma unroll
    for (int ii = 0; ii < 8; ii++) {
        m_i[ii] = -1e30f; l_i[ii] = 0.f;
#pragma unroll
        for (int dd = 0; dd < 4; dd++) o[ii][dd] = 0.f;
    }

    for (int j0 = 0; j0 < SEQ; j0 += BJ) {
        // Load K tile transposed: Kt[d][j]
#pragma unroll
        for (int it = 0; it < 4; it++) {
            int fidx = t + it*256;         // 1024 float4s
            int j    = fidx >> 4;          // 0..63
            int d0   = (fidx & 15) * 4;
            float4 v = *(const float4*)&kg[(size_t)(j0 + j)*HD + d0];
            Kt[d0+0][j] = v.x; Kt[d0+1][j] = v.y;
            Kt[d0+2][j] = v.z; Kt[d0+3][j] = v.w;
        }
        // Load V tile direct: Vs[j][d]
#pragma unroll
        for (int it = 0; it < 4; it++) {
            int fidx = t + it*256;
            int j    = fidx >> 4;
            int d0   = (fidx & 15) * 4;
            *(float4*)&Vs[j][d0] = *(const float4*)&vg[(size_t)(j0 + j)*HD + d0];
        }
        __syncthreads();

        // QK^T: s[ii][jj] = sum_d Qt[d][ty*8+ii] * Kt[d][tx*4+jj]
        float s[8][4];
#pragma unroll
        for (int ii = 0; ii < 8; ii++)
#pragma unroll
            for (int jj = 0; jj < 4; jj++) s[ii][jj] = 0.f;

#pragma unroll 8
        for (int d = 0; d < 64; d++) {
            float4 q0 = *(const float4*)&Qt[d][ty*8];
            float4 q1 = *(const float4*)&Qt[d][ty*8+4];
            float4 kv = *(const float4*)&Kt[d][tx*4];
            float qa[8] = {q0.x,q0.y,q0.z,q0.w,q1.x,q1.y,q1.z,q1.w};
            float kb[4] = {kv.x,kv.y,kv.z,kv.w};
#pragma unroll
            for (int ii = 0; ii < 8; ii++)
#pragma unroll
                for (int jj = 0; jj < 4; jj++)
                    s[ii][jj] += qa[ii] * kb[jj];
        }

        // Scale + band mask, online softmax (row spread over 16 tx lanes).
#pragma unroll
        for (int ii = 0; ii < 8; ii++) {
            const int ig = i0 + ty*8 + ii;
#pragma unroll
            for (int jj = 0; jj < 4; jj++) {
                int jg = j0 + tx*4 + jj;
                int dij = ig - jg; if (dij < 0) dij = -dij;
                float band = (dij <= 2) ? 0.1f : 0.f;
                s[ii][jj] = s[ii][jj] * 0.125f + band;
            }
        }

#pragma unroll
        for (int ii = 0; ii < 8; ii++) {
            float mt = fmaxf(fmaxf(s[ii][0], s[ii][1]), fmaxf(s[ii][2], s[ii][3]));
            mt = fmaxf(mt, __shfl_xor_sync(0xffffffffu, mt, 1));
            mt = fmaxf(mt, __shfl_xor_sync(0xffffffffu, mt, 2));
            mt = fmaxf(mt, __shfl_xor_sync(0xffffffffu, mt, 4));
            mt = fmaxf(mt, __shfl_xor_sync(0xffffffffu, mt, 8));
            float m_new = fmaxf(m_i[ii], mt);
            float alpha = __expf(m_i[ii] - m_new);
            m_i[ii] = m_new;
            float sum = 0.f;
#pragma unroll
            for (int jj = 0; jj < 4; jj++) {
                float p = __expf(s[ii][jj] - m_new);
                s[ii][jj] = p;
                sum += p;
            }
            sum += __shfl_xor_sync(0xffffffffu, sum, 1);
            sum += __shfl_xor_sync(0xffffffffu, sum, 2);
            sum += __shfl_xor_sync(0xffffffffu, sum, 4);
            sum += __shfl_xor_sync(0xffffffffu, sum, 8);
            l_i[ii] = l_i[ii] * alpha + sum;
#pragma unroll
            for (int dd = 0; dd < 4; dd++) o[ii][dd] *= alpha;
        }

        // Store P transposed: Pt[j][i]
#pragma unroll
        for (int jj = 0; jj < 4; jj++)
#pragma unroll
            for (int ii = 0; ii < 8; ii++)
                Pt[tx*4 + jj][ty*8 + ii] = s[ii][jj];
        __syncthreads();

        // PV: o[ii][dd] += sum_j Pt[j][ty*8+ii] * Vs[j][tx*4+dd]
#pragma unroll 8
        for (int j = 0; j < 64; j++) {
            float4 p0 = *(const float4*)&Pt[j][ty*8];
            float4 p1 = *(const float4*)&Pt[j][ty*8+4];
            float4 vv = *(const float4*)&Vs[j][tx*4];
            float pa[8] = {p0.x,p0.y,p0.z,p0.w,p1.x,p1.y,p1.z,p1.w};
            float vb[4] = {vv.x,vv.y,vv.z,vv.w};
#pragma unroll
            for (int ii = 0; ii < 8; ii++)
#pragma unroll
                for (int dd = 0; dd < 4; dd++)
                    o[ii][dd] += pa[ii] * vb[dd];
        }
        __syncthreads();
    }

    // Write normalized output in flat [B,S,D] layout for the O-projection GEMM.
    const int b = bh >> 4, h = bh & 15;
#pragma unroll
    for (int ii = 0; ii < 8; ii++) {
        const float inv = 1.f / l_i[ii];
        float4 v;
        v.x = o[ii][0]*inv; v.y = o[ii][1]*inv;
        v.z = o[ii][2]*inv; v.w = o[ii][3]*inv;
        float* op = out + ((size_t)(b*SEQ + i0 + ty*8 + ii)) * DM + h*HD + tx*4;
        *(float4*)op = v;
    }
}

// ---------------------------------------------------------------------------
extern "C" void kernel_launch(void* const* d_in, const int* in_sizes, int n_in,
                              void* d_out, int out_size)
{
    const float* x        = (const float*)d_in[0];
    // d_in[1] = ocr_context: shape-only in reference, unused
    const float* Wq       = (const float*)d_in[2];
    const float* bq       = (const float*)d_in[3];
    const float* Wk       = (const float*)d_in[4];
    const float* bk       = (const float*)d_in[5];
    const float* Wv       = (const float*)d_in[6];
    const float* bv       = (const float*)d_in[7];
    const float* Wo       = (const float*)d_in[8];
    const float* bo       = (const float*)d_in[9];
    const float* ocr_bias = (const float*)d_in[10];

    float *qp, *kp, *vp, *ap;
    cudaGetSymbolAddress((void**)&qp, g_q);
    cudaGetSymbolAddress((void**)&kp, g_k);
    cudaGetSymbolAddress((void**)&vp, g_v);
    cudaGetSymbolAddress((void**)&ap, g_attn);

    cudaFuncSetAttribute(attn_kernel,
                         cudaFuncAttributeMaxDynamicSharedMemorySize, ATTN_SMEM);

    dim3 gemm_grid(DM/128, MROWS/128);   // (8, 64)
    gemm_nt_kernel<<<gemm_grid, 256>>>(x, Wq, bq, ocr_bias, qp, 1);
    gemm_nt_kernel<<<gemm_grid, 256>>>(x, Wk, bk, nullptr,  kp, 1);
    gemm_nt_kernel<<<gemm_grid, 256>>>(x, Wv, bv, nullptr,  vp, 1);

    dim3 attn_grid(SEQ/BQ, NB*NH);       // (16, 64)
    attn_kernel<<<attn_grid, 256, ATTN_SMEM>>>(ap);

    gemm_nt_kernel<<<gemm_grid, 256>>>(ap, Wo, bo, nullptr, (float*)d_out, 0);
}